// round 1
// baseline (speedup 1.0000x reference)
#include <cuda_runtime.h>
#include <cuda_bf16.h>
#include <cstdint>

// Problem constants
#define BATCH 4096
#define NSEQ  64
#define FIN   128
#define HDIM  512   // H*D
#define NHEAD 8

typedef unsigned long long ull;

// ---------- f32x2 packed math (sm_103a FFMA2 path) ----------
__device__ __forceinline__ ull pk2(float x, float y) {
    ull r; asm("mov.b64 %0, {%1,%2};" : "=l"(r) : "f"(x), "f"(y)); return r;
}
__device__ __forceinline__ void fma2(ull& d, ull a, ull b) {
    asm("fma.rn.f32x2 %0, %1, %2, %0;" : "+l"(d) : "l"(a), "l"(b));
}
__device__ __forceinline__ float2 up2(ull v) {
    float2 f; asm("mov.b64 {%0,%1}, %2;" : "=f"(f.x), "=f"(f.y) : "l"(v)); return f;
}

// ---------- cp.async ----------
__device__ __forceinline__ void cp_async16(void* s, const void* g) {
    unsigned sa = (unsigned)__cvta_generic_to_shared(s);
    asm volatile("cp.async.cg.shared.global [%0], [%1], 16;" :: "r"(sa), "l"(g));
}
__device__ __forceinline__ void cp_commit() { asm volatile("cp.async.commit_group;"); }
template<int N> __device__ __forceinline__ void cp_wait() {
    asm volatile("cp.async.wait_group %0;" :: "n"(N));
}

// ---------- shared memory layout (float offsets) ----------
// GEMM phase:
//   xsT  [128][68]   @ 0       (8704 floats)  x transposed, padded row=68
//   ws0  [16][512]   @ 8704
//   ws1  [16][512]   @ 16896   (ends 25088)
// Post-GEMM phase (linS overwrites dead xsT/ws region):
//   linS [64][516]   @ 0       (33024 floats)
//   WattT[8][1028]   @ 33024   (loaded early; outside GEMM region)
//   attS [64][8]     @ 41248
//   att0 [8]         @ 41760
//   awS  [8][64]     @ 41768
//   mask int[64]     @ 42280
#define OFF_XST  0
#define OFF_WS0  8704
#define OFF_WS1  16896
#define OFF_LIN  0
#define OFF_WATT 33024
#define OFF_ATT  41248
#define OFF_ATT0 41760
#define OFF_AW   41768
#define OFF_MASK 42280
#define SMEM_FLOATS 42344
#define SMEM_BYTES  (SMEM_FLOATS * 4)

__global__ void __launch_bounds__(512, 1)
agg_kernel(const float* __restrict__ x, const float* __restrict__ Wlin,
           const float* __restrict__ Watt, const int* __restrict__ mask,
           float* __restrict__ out)
{
    extern __shared__ float sm[];
    const int t    = threadIdx.x;
    const int b    = blockIdx.x;
    const int ty   = t >> 6;        // 0..7  (row tile)
    const int tx   = t & 63;        // 0..63 (col tile)
    const int lane = t & 31;

    float* xsT = sm + OFF_XST;

    // --- kick off W_lin stage 0 (cp.async) ---
    {
        #pragma unroll
        for (int it = 0; it < 4; ++it) {
            int v = t + it * 512;                 // 0..2047 float4 units
            cp_async16(sm + OFF_WS0 + v * 4, Wlin + v * 4);
        }
        cp_commit();
    }

    // --- load W_att transposed: WattT[h][c] = Watt[c*8+h] ---
    for (int v = t; v < 2 * HDIM * NHEAD; v += 512) {
        int c = v >> 3, h = v & 7;
        sm[OFF_WATT + h * 1028 + c] = Watt[v];
    }
    // --- mask ---
    if (t < NSEQ) ((int*)(sm + OFF_MASK))[t] = mask[b * NSEQ + t];

    // --- load x_b transposed into xsT[k][r], row pad 68 ---
    const float* xb = x + (size_t)b * NSEQ * FIN;
    #pragma unroll
    for (int it = 0; it < 4; ++it) {
        int v  = t + it * 512;                    // 0..2047
        int k  = (v & 31) + (((v >> 5) & 3) << 5);
        int rb = (v >> 7) << 2;
        float4 f;
        f.x = xb[(rb + 0) * FIN + k];
        f.y = xb[(rb + 1) * FIN + k];
        f.z = xb[(rb + 2) * FIN + k];
        f.w = xb[(rb + 3) * FIN + k];
        *(float4*)(xsT + k * 68 + rb) = f;
    }

    // --- GEMM: lin[64][512] = x_b[64][128] @ W_lin[128][512] ---
    // thread tile: rows ty*8..ty*8+7 (4 packed pairs), cols cg0..cg0+3, cg1..cg1+3
    ull acc[32];
    #pragma unroll
    for (int i = 0; i < 32; ++i) acc[i] = 0ull;

    const int ty4 = ty * 4;
    const int ci0 = (tx & 15) + ((tx >> 4) << 4);  // float4 col index, group 0
    const int ci1 = ci0 + 64;                       // group 1 (+256 floats)

    for (int s = 0; s < 8; ++s) {
        __syncthreads();   // prior consumers of dst buffer done; (s=0) xsT ready
        if (s < 7) {
            const float* wsrc = Wlin + (size_t)(s + 1) * 16 * HDIM;
            float* dst = sm + ((s & 1) ? OFF_WS0 : OFF_WS1);  // buffer (s+1)&1
            #pragma unroll
            for (int it = 0; it < 4; ++it) {
                int v = t + it * 512;
                cp_async16(dst + v * 4, wsrc + v * 4);
            }
            cp_commit();
            cp_wait<1>();   // stage s arrived, stage s+1 in flight
        } else {
            cp_wait<0>();
        }
        __syncthreads();

        const float4* w4 = (const float4*)(sm + ((s & 1) ? OFF_WS1 : OFF_WS0));
        const ull*    au = (const ull*)xsT;   // 34 ull per row
        const int kbase = s * 16;
        #pragma unroll
        for (int k = 0; k < 16; ++k) {
            int arow = (kbase + k) * 34 + ty4;
            ull a0 = au[arow + 0], a1 = au[arow + 1];
            ull a2 = au[arow + 2], a3 = au[arow + 3];
            float4 b0 = w4[k * 128 + ci0];
            float4 b1 = w4[k * 128 + ci1];
            ull d00 = pk2(b0.x, b0.x), d01 = pk2(b0.y, b0.y);
            ull d02 = pk2(b0.z, b0.z), d03 = pk2(b0.w, b0.w);
            ull d10 = pk2(b1.x, b1.x), d11 = pk2(b1.y, b1.y);
            ull d12 = pk2(b1.z, b1.z), d13 = pk2(b1.w, b1.w);
            #pragma unroll
            for (int p = 0; p < 4; ++p) {
                ull ap = (p == 0) ? a0 : (p == 1) ? a1 : (p == 2) ? a2 : a3;
                fma2(acc[p * 8 + 0], ap, d00); fma2(acc[p * 8 + 1], ap, d01);
                fma2(acc[p * 8 + 2], ap, d02); fma2(acc[p * 8 + 3], ap, d03);
                fma2(acc[p * 8 + 4], ap, d10); fma2(acc[p * 8 + 5], ap, d11);
                fma2(acc[p * 8 + 6], ap, d12); fma2(acc[p * 8 + 7], ap, d13);
            }
        }
    }

    // --- spill lin to smem (overwrites dead xsT/ws region) ---
    __syncthreads();
    float* linS = sm + OFF_LIN;
    const int cg0 = ci0 * 4;         // 4*(tx&15) + 64*(tx>>4)
    const int cg1 = cg0 + 256;
    #pragma unroll
    for (int p = 0; p < 4; ++p) {
        int rlo = ty * 8 + 2 * p;
        #pragma unroll
        for (int g = 0; g < 2; ++g) {
            float2 e0 = up2(acc[p * 8 + g * 4 + 0]);
            float2 e1 = up2(acc[p * 8 + g * 4 + 1]);
            float2 e2 = up2(acc[p * 8 + g * 4 + 2]);
            float2 e3 = up2(acc[p * 8 + g * 4 + 3]);
            int cg = g ? cg1 : cg0;
            *(float4*)(linS + rlo * 516 + cg)       = make_float4(e0.x, e1.x, e2.x, e3.x);
            *(float4*)(linS + (rlo + 1) * 516 + cg) = make_float4(e0.y, e1.y, e2.y, e3.y);
        }
    }
    __syncthreads();

    // --- attention logits: one (n,h) per thread ---
    {
        const int n  = t >> 3;
        const int hh = t & 7;
        const ulonglong2* lr = (const ulonglong2*)(linS + n * 516);
        const ulonglong2* w2 = (const ulonglong2*)(sm + OFF_WATT + hh * 1028 + HDIM);
        ull s0 = 0, s1 = 0;
        #pragma unroll 8
        for (int q = 0; q < 128; ++q) {
            ulonglong2 lv = lr[q], wv = w2[q];
            fma2(s0, lv.x, wv.x);
            fma2(s1, lv.y, wv.y);
        }
        float2 f0 = up2(s0), f1 = up2(s1);
        float dot = (f0.x + f0.y) + (f1.x + f1.y);

        if (t < 8) {   // src term: lin[0,:] @ W_att[:HD], head = t
            const ulonglong2* l0 = (const ulonglong2*)linS;
            const ulonglong2* w1 = (const ulonglong2*)(sm + OFF_WATT + t * 1028);
            ull u0 = 0, u1 = 0;
            #pragma unroll 8
            for (int q = 0; q < 128; ++q) {
                ulonglong2 lv = l0[q], wv = w1[q];
                fma2(u0, lv.x, wv.x);
                fma2(u1, lv.y, wv.y);
            }
            float2 g0 = up2(u0), g1 = up2(u1);
            sm[OFF_ATT0 + t] = (g0.x + g0.y) + (g1.x + g1.y);
        }
        __syncthreads();
        float v = sm[OFF_ATT0 + hh] + dot;
        v = (v >= 0.f) ? v : 0.2f * v;     // leaky relu (before mask, per reference)
        sm[OFF_ATT + n * 8 + hh] = v;
    }
    __syncthreads();

    // --- softmax over n per head: warp w handles head w ---
    {
        int w = t >> 5;
        if (w < 8) {
            const int* mk = (const int*)(sm + OFF_MASK);
            float v0 = sm[OFF_ATT + lane * 8 + w]        + (mk[lane]      == 0 ? -1e9f : 0.f);
            float v1 = sm[OFF_ATT + (lane + 32) * 8 + w] + (mk[lane + 32] == 0 ? -1e9f : 0.f);
            float m = fmaxf(v0, v1);
            #pragma unroll
            for (int o = 16; o > 0; o >>= 1) m = fmaxf(m, __shfl_xor_sync(0xffffffffu, m, o));
            float e0 = __expf(v0 - m), e1 = __expf(v1 - m);
            float ssum = e0 + e1;
            #pragma unroll
            for (int o = 16; o > 0; o >>= 1) ssum += __shfl_xor_sync(0xffffffffu, ssum, o);
            float inv = 1.f / ssum;
            sm[OFF_AW + w * 64 + lane]      = e0 * inv;
            sm[OFF_AW + w * 64 + lane + 32] = e1 * inv;
        }
    }
    __syncthreads();

    // --- epilogue: out = relu(lin * aw[h][n]), from live registers ---
    {
        float* ob = out + (size_t)b * (NSEQ * HDIM);
        int h0 = tx >> 4;
        float aw0[8], aw1[8];
        #pragma unroll
        for (int i = 0; i < 8; ++i) {
            aw0[i] = sm[OFF_AW + h0 * 64 + ty * 8 + i];
            aw1[i] = sm[OFF_AW + (h0 + 4) * 64 + ty * 8 + i];
        }
        #pragma unroll
        for (int p = 0; p < 4; ++p) {
            int rlo = ty * 8 + 2 * p;
            #pragma unroll
            for (int g = 0; g < 2; ++g) {
                float2 e0 = up2(acc[p * 8 + g * 4 + 0]);
                float2 e1 = up2(acc[p * 8 + g * 4 + 1]);
                float2 e2 = up2(acc[p * 8 + g * 4 + 2]);
                float2 e3 = up2(acc[p * 8 + g * 4 + 3]);
                const float* aw = g ? aw1 : aw0;
                int cg = g ? cg1 : cg0;
                float slo = aw[2 * p], shi = aw[2 * p + 1];
                float4 lo = make_float4(fmaxf(e0.x * slo, 0.f), fmaxf(e1.x * slo, 0.f),
                                        fmaxf(e2.x * slo, 0.f), fmaxf(e3.x * slo, 0.f));
                float4 hi = make_float4(fmaxf(e0.y * shi, 0.f), fmaxf(e1.y * shi, 0.f),
                                        fmaxf(e2.y * shi, 0.f), fmaxf(e3.y * shi, 0.f));
                *(float4*)(ob + (size_t)rlo * HDIM + cg)       = lo;
                *(float4*)(ob + (size_t)(rlo + 1) * HDIM + cg) = hi;
            }
        }
    }
}

extern "C" void kernel_launch(void* const* d_in, const int* in_sizes, int n_in,
                              void* d_out, int out_size)
{
    const float* x    = (const float*)d_in[0];
    const float* Wlin = (const float*)d_in[1];
    const float* Watt = (const float*)d_in[2];
    const int*   mk   = (const int*)d_in[3];
    float*       out  = (float*)d_out;

    cudaFuncSetAttribute(agg_kernel, cudaFuncAttributeMaxDynamicSharedMemorySize, SMEM_BYTES);
    agg_kernel<<<BATCH, 512, SMEM_BYTES>>>(x, Wlin, Watt, mk, out);
}

// round 2
// speedup vs baseline: 1.0003x; 1.0003x over previous
#include <cuda_runtime.h>
#include <cuda_bf16.h>
#include <cstdint>

// Problem constants
#define BATCH 4096
#define NSEQ  64
#define FIN   128
#define HDIM  512   // H*D
#define NHEAD 8

typedef unsigned long long ull;

// ---------- f32x2 packed math (sm_103a FFMA2 path) ----------
__device__ __forceinline__ ull pk2(float x, float y) {
    ull r; asm("mov.b64 %0, {%1,%2};" : "=l"(r) : "f"(x), "f"(y)); return r;
}
__device__ __forceinline__ void fma2(ull& d, ull a, ull b) {
    asm("fma.rn.f32x2 %0, %1, %2, %0;" : "+l"(d) : "l"(a), "l"(b));
}
__device__ __forceinline__ float2 up2(ull v) {
    float2 f; asm("mov.b64 {%0,%1}, %2;" : "=f"(f.x), "=f"(f.y) : "l"(v)); return f;
}

// ---------- cp.async ----------
__device__ __forceinline__ void cp_async16(void* s, const void* g) {
    unsigned sa = (unsigned)__cvta_generic_to_shared(s);
    asm volatile("cp.async.cg.shared.global [%0], [%1], 16;" :: "r"(sa), "l"(g));
}
__device__ __forceinline__ void cp_commit() { asm volatile("cp.async.commit_group;"); }
template<int N> __device__ __forceinline__ void cp_wait() {
    asm volatile("cp.async.wait_group %0;" :: "n"(N));
}

// ---------- shared memory layout (float offsets) ----------
// GEMM phase:
//   xsT  [128][68]   @ 0       (8704 floats)  x transposed, padded row=68
//   ws0  [16][512]   @ 8704
//   ws1  [16][512]   @ 16896   (ends 25088)
// Post-GEMM phase (linS overwrites dead xsT/ws region):
//   linS [64][516]   @ 0       (33024 floats)
//   WattT[8][1028]   @ 33024   (loaded early; outside GEMM region)
//   attS [64][8]     @ 41248
//   att0 [8]         @ 41760
//   awS  [8][64]     @ 41768
//   mask int[64]     @ 42280
#define OFF_XST  0
#define OFF_WS0  8704
#define OFF_WS1  16896
#define OFF_LIN  0
#define OFF_WATT 33024
#define OFF_ATT  41248
#define OFF_ATT0 41760
#define OFF_AW   41768
#define OFF_MASK 42280
#define SMEM_FLOATS 42344
#define SMEM_BYTES  (SMEM_FLOATS * 4)

__global__ void __launch_bounds__(512, 1)
agg_kernel(const float* __restrict__ x, const float* __restrict__ Wlin,
           const float* __restrict__ Watt, const int* __restrict__ mask,
           float* __restrict__ out)
{
    extern __shared__ float sm[];
    const int t    = threadIdx.x;
    const int b    = blockIdx.x;
    const int ty   = t >> 6;        // 0..7  (row tile)
    const int tx   = t & 63;        // 0..63 (col tile)
    const int lane = t & 31;

    float* xsT = sm + OFF_XST;

    // --- kick off W_lin stage 0 (cp.async) ---
    {
        #pragma unroll
        for (int it = 0; it < 4; ++it) {
            int v = t + it * 512;                 // 0..2047 float4 units
            cp_async16(sm + OFF_WS0 + v * 4, Wlin + v * 4);
        }
        cp_commit();
    }

    // --- load W_att transposed: WattT[h][c] = Watt[c*8+h] ---
    for (int v = t; v < 2 * HDIM * NHEAD; v += 512) {
        int c = v >> 3, h = v & 7;
        sm[OFF_WATT + h * 1028 + c] = Watt[v];
    }
    // --- mask ---
    if (t < NSEQ) ((int*)(sm + OFF_MASK))[t] = mask[b * NSEQ + t];

    // --- load x_b transposed into xsT[k][r], row pad 68 ---
    const float* xb = x + (size_t)b * NSEQ * FIN;
    #pragma unroll
    for (int it = 0; it < 4; ++it) {
        int v  = t + it * 512;                    // 0..2047
        int k  = (v & 31) + (((v >> 5) & 3) << 5);
        int rb = (v >> 7) << 2;
        float4 f;
        f.x = xb[(rb + 0) * FIN + k];
        f.y = xb[(rb + 1) * FIN + k];
        f.z = xb[(rb + 2) * FIN + k];
        f.w = xb[(rb + 3) * FIN + k];
        *(float4*)(xsT + k * 68 + rb) = f;
    }

    // --- GEMM: lin[64][512] = x_b[64][128] @ W_lin[128][512] ---
    // thread tile: rows ty*8..ty*8+7 (4 packed pairs), cols cg0..cg0+3, cg1..cg1+3
    ull acc[32];
    #pragma unroll
    for (int i = 0; i < 32; ++i) acc[i] = 0ull;

    const int ty4 = ty * 4;
    const int ci0 = (tx & 15) + ((tx >> 4) << 4);  // float4 col index, group 0
    const int ci1 = ci0 + 64;                       // group 1 (+256 floats)

    for (int s = 0; s < 8; ++s) {
        __syncthreads();   // prior consumers of dst buffer done; (s=0) xsT ready
        if (s < 7) {
            const float* wsrc = Wlin + (size_t)(s + 1) * 16 * HDIM;
            float* dst = sm + ((s & 1) ? OFF_WS0 : OFF_WS1);  // buffer (s+1)&1
            #pragma unroll
            for (int it = 0; it < 4; ++it) {
                int v = t + it * 512;
                cp_async16(dst + v * 4, wsrc + v * 4);
            }
            cp_commit();
            cp_wait<1>();   // stage s arrived, stage s+1 in flight
        } else {
            cp_wait<0>();
        }
        __syncthreads();

        const float4* w4 = (const float4*)(sm + ((s & 1) ? OFF_WS1 : OFF_WS0));
        const ull*    au = (const ull*)xsT;   // 34 ull per row
        const int kbase = s * 16;
        #pragma unroll
        for (int k = 0; k < 16; ++k) {
            int arow = (kbase + k) * 34 + ty4;
            ull a0 = au[arow + 0], a1 = au[arow + 1];
            ull a2 = au[arow + 2], a3 = au[arow + 3];
            float4 b0 = w4[k * 128 + ci0];
            float4 b1 = w4[k * 128 + ci1];
            ull d00 = pk2(b0.x, b0.x), d01 = pk2(b0.y, b0.y);
            ull d02 = pk2(b0.z, b0.z), d03 = pk2(b0.w, b0.w);
            ull d10 = pk2(b1.x, b1.x), d11 = pk2(b1.y, b1.y);
            ull d12 = pk2(b1.z, b1.z), d13 = pk2(b1.w, b1.w);
            #pragma unroll
            for (int p = 0; p < 4; ++p) {
                ull ap = (p == 0) ? a0 : (p == 1) ? a1 : (p == 2) ? a2 : a3;
                fma2(acc[p * 8 + 0], ap, d00); fma2(acc[p * 8 + 1], ap, d01);
                fma2(acc[p * 8 + 2], ap, d02); fma2(acc[p * 8 + 3], ap, d03);
                fma2(acc[p * 8 + 4], ap, d10); fma2(acc[p * 8 + 5], ap, d11);
                fma2(acc[p * 8 + 6], ap, d12); fma2(acc[p * 8 + 7], ap, d13);
            }
        }
    }

    // --- spill lin to smem (overwrites dead xsT/ws region) ---
    __syncthreads();
    float* linS = sm + OFF_LIN;
    const int cg0 = ci0 * 4;         // 4*(tx&15) + 64*(tx>>4)
    const int cg1 = cg0 + 256;
    #pragma unroll
    for (int p = 0; p < 4; ++p) {
        int rlo = ty * 8 + 2 * p;
        #pragma unroll
        for (int g = 0; g < 2; ++g) {
            float2 e0 = up2(acc[p * 8 + g * 4 + 0]);
            float2 e1 = up2(acc[p * 8 + g * 4 + 1]);
            float2 e2 = up2(acc[p * 8 + g * 4 + 2]);
            float2 e3 = up2(acc[p * 8 + g * 4 + 3]);
            int cg = g ? cg1 : cg0;
            *(float4*)(linS + rlo * 516 + cg)       = make_float4(e0.x, e1.x, e2.x, e3.x);
            *(float4*)(linS + (rlo + 1) * 516 + cg) = make_float4(e0.y, e1.y, e2.y, e3.y);
        }
    }
    __syncthreads();

    // --- attention logits: one (n,h) per thread ---
    {
        const int n  = t >> 3;
        const int hh = t & 7;
        const ulonglong2* lr = (const ulonglong2*)(linS + n * 516);
        const ulonglong2* w2 = (const ulonglong2*)(sm + OFF_WATT + hh * 1028 + HDIM);
        ull s0 = 0, s1 = 0;
        #pragma unroll 8
        for (int q = 0; q < 128; ++q) {
            ulonglong2 lv = lr[q], wv = w2[q];
            fma2(s0, lv.x, wv.x);
            fma2(s1, lv.y, wv.y);
        }
        float2 f0 = up2(s0), f1 = up2(s1);
        float dot = (f0.x + f0.y) + (f1.x + f1.y);

        if (t < 8) {   // src term: lin[0,:] @ W_att[:HD], head = t
            const ulonglong2* l0 = (const ulonglong2*)linS;
            const ulonglong2* w1 = (const ulonglong2*)(sm + OFF_WATT + t * 1028);
            ull u0 = 0, u1 = 0;
            #pragma unroll 8
            for (int q = 0; q < 128; ++q) {
                ulonglong2 lv = l0[q], wv = w1[q];
                fma2(u0, lv.x, wv.x);
                fma2(u1, lv.y, wv.y);
            }
            float2 g0 = up2(u0), g1 = up2(u1);
            sm[OFF_ATT0 + t] = (g0.x + g0.y) + (g1.x + g1.y);
        }
        __syncthreads();
        float v = sm[OFF_ATT0 + hh] + dot;
        v = (v >= 0.f) ? v : 0.2f * v;     // leaky relu (before mask, per reference)
        sm[OFF_ATT + n * 8 + hh] = v;
    }
    __syncthreads();

    // --- softmax over n per head: warp w handles head w ---
    {
        int w = t >> 5;
        if (w < 8) {
            const int* mk = (const int*)(sm + OFF_MASK);
            float v0 = sm[OFF_ATT + lane * 8 + w]        + (mk[lane]      == 0 ? -1e9f : 0.f);
            float v1 = sm[OFF_ATT + (lane + 32) * 8 + w] + (mk[lane + 32] == 0 ? -1e9f : 0.f);
            float m = fmaxf(v0, v1);
            #pragma unroll
            for (int o = 16; o > 0; o >>= 1) m = fmaxf(m, __shfl_xor_sync(0xffffffffu, m, o));
            float e0 = __expf(v0 - m), e1 = __expf(v1 - m);
            float ssum = e0 + e1;
            #pragma unroll
            for (int o = 16; o > 0; o >>= 1) ssum += __shfl_xor_sync(0xffffffffu, ssum, o);
            float inv = 1.f / ssum;
            sm[OFF_AW + w * 64 + lane]      = e0 * inv;
            sm[OFF_AW + w * 64 + lane + 32] = e1 * inv;
        }
    }
    __syncthreads();

    // --- epilogue: out = relu(lin * aw[h][n]), from live registers ---
    {
        float* ob = out + (size_t)b * (NSEQ * HDIM);
        int h0 = tx >> 4;
        float aw0[8], aw1[8];
        #pragma unroll
        for (int i = 0; i < 8; ++i) {
            aw0[i] = sm[OFF_AW + h0 * 64 + ty * 8 + i];
            aw1[i] = sm[OFF_AW + (h0 + 4) * 64 + ty * 8 + i];
        }
        #pragma unroll
        for (int p = 0; p < 4; ++p) {
            int rlo = ty * 8 + 2 * p;
            #pragma unroll
            for (int g = 0; g < 2; ++g) {
                float2 e0 = up2(acc[p * 8 + g * 4 + 0]);
                float2 e1 = up2(acc[p * 8 + g * 4 + 1]);
                float2 e2 = up2(acc[p * 8 + g * 4 + 2]);
                float2 e3 = up2(acc[p * 8 + g * 4 + 3]);
                const float* aw = g ? aw1 : aw0;
                int cg = g ? cg1 : cg0;
                float slo = aw[2 * p], shi = aw[2 * p + 1];
                float4 lo = make_float4(fmaxf(e0.x * slo, 0.f), fmaxf(e1.x * slo, 0.f),
                                        fmaxf(e2.x * slo, 0.f), fmaxf(e3.x * slo, 0.f));
                float4 hi = make_float4(fmaxf(e0.y * shi, 0.f), fmaxf(e1.y * shi, 0.f),
                                        fmaxf(e2.y * shi, 0.f), fmaxf(e3.y * shi, 0.f));
                *(float4*)(ob + (size_t)rlo * HDIM + cg)       = lo;
                *(float4*)(ob + (size_t)(rlo + 1) * HDIM + cg) = hi;
            }
        }
    }
}

extern "C" void kernel_launch(void* const* d_in, const int* in_sizes, int n_in,
                              void* d_out, int out_size)
{
    const float* x    = (const float*)d_in[0];
    const float* Wlin = (const float*)d_in[1];
    const float* Watt = (const float*)d_in[2];
    const int*   mk   = (const int*)d_in[3];
    float*       out  = (float*)d_out;

    cudaFuncSetAttribute(agg_kernel, cudaFuncAttributeMaxDynamicSharedMemorySize, SMEM_BYTES);
    agg_kernel<<<BATCH, 512, SMEM_BYTES>>>(x, Wlin, Watt, mk, out);
}

// round 4
// speedup vs baseline: 2.0262x; 2.0256x over previous
#include <cuda_runtime.h>
#include <cuda_bf16.h>
#include <cstdint>

#define BATCH  4096
#define NPAIR  (BATCH / 2)

// ---------------- device-global staging (written by pre-kernels) ----------------
// gWimg[split][131072]: per split, layout [nblk 64][kblk 8][tile 256B],
//   tile = 8 n-rows x 16 k bf16, row n at ((n*32 + kh*16) ^ ((n&4)?16:0)) + (k&7)*2
__device__ __align__(1024) unsigned char gWimg[2][131072];
// gT[half][f][h] = sum_c Wlin[f][c] * Watt[(half*512 + c)*8 + h]
__device__ __align__(16) float gT[2][128][8];

// ---------------- PTX helpers ----------------
__device__ __forceinline__ uint32_t smem_u32(const void* p) {
    uint32_t a;
    asm("{ .reg .u64 t; cvta.to.shared.u64 t, %1; cvt.u32.u64 %0, t; }" : "=r"(a) : "l"(p));
    return a;
}
__device__ __forceinline__ void cp_async16(uint32_t saddr, const void* g) {
    asm volatile("cp.async.cg.shared.global [%0], [%1], 16;" :: "r"(saddr), "l"(g));
}
__device__ __forceinline__ void cp_commit() { asm volatile("cp.async.commit_group;"); }
template<int N> __device__ __forceinline__ void cp_wait() {
    asm volatile("cp.async.wait_group %0;" :: "n"(N));
}

#define LDSM_X4(d, a)                                                             \
    asm volatile("ldmatrix.sync.aligned.m8n8.x4.shared.b16 {%0,%1,%2,%3}, [%4];"  \
        : "=r"((d)[0]), "=r"((d)[1]), "=r"((d)[2]), "=r"((d)[3]) : "r"(a))

__device__ __forceinline__ void mma16816(float* c, const uint32_t* a,
                                         uint32_t b0, uint32_t b1) {
    asm volatile("mma.sync.aligned.m16n8k16.row.col.f32.bf16.bf16.f32 "
        "{%0,%1,%2,%3}, {%4,%5,%6,%7}, {%8,%9}, {%0,%1,%2,%3};"
        : "+f"(c[0]), "+f"(c[1]), "+f"(c[2]), "+f"(c[3])
        : "r"(a[0]), "r"(a[1]), "r"(a[2]), "r"(a[3]), "r"(b0), "r"(b1));
}

__device__ __forceinline__ uint32_t pkbf2(__nv_bfloat16 a, __nv_bfloat16 b) {
    __nv_bfloat162 t; t.x = a; t.y = b;
    return *reinterpret_cast<uint32_t*>(&t);
}

// ---------------- pre-kernel 1: T = Wlin @ Watt halves ----------------
__global__ void k_prepT(const float* __restrict__ Wlin, const float* __restrict__ Watt) {
    int idx = blockIdx.x * blockDim.x + threadIdx.x;   // 2048
    int half = idx >> 10, f = (idx >> 3) & 127, h = idx & 7;
    float acc = 0.f;
    for (int c = 0; c < 512; ++c)
        acc += Wlin[f * 512 + c] * Watt[(half * 512 + c) * 8 + h];
    gT[half][f][h] = acc;
}

// ---------------- pre-kernel 2: W -> bf16-split ldmatrix tile images ----------------
__global__ void k_prepW(const float* __restrict__ Wlin) {
    int idx = blockIdx.x * blockDim.x + threadIdx.x;   // 65536
    int n = idx >> 7, k = idx & 127;
    float v = Wlin[k * 512 + n];
    __nv_bfloat16 hi = __float2bfloat16(v);
    __nv_bfloat16 lo = __float2bfloat16(v - __bfloat162float(hi));
    int nblk = n >> 3, nr = n & 7, kblk = k >> 4, kk = k & 15, kh = kk >> 3;
    uint32_t off = (uint32_t)nblk * 2048u + (uint32_t)kblk * 256u
                 + (((uint32_t)nr * 32u + (uint32_t)kh * 16u) ^ ((nr & 4) ? 16u : 0u))
                 + (uint32_t)(kk & 7) * 2u;
    *(__nv_bfloat16*)(&gWimg[0][off]) = hi;
    *(__nv_bfloat16*)(&gWimg[1][off]) = lo;
}

// ---------------- main kernel ----------------
// SMEM map (bytes):
#define SM_X     0           // x fp32 stage [128][128] (64KB)
#define SM_A     65536       // A bf16 tile images: [split][mblk 8][kblk 8][512B] (64KB)
#define SM_B     131072      // B double buffer: 2 x [split][nblk 8][kblk 8][256B] (64KB)
#define SM_SS    196608      // S[2][8] fp32
#define SM_ATT   196672      // att/aw [2][8][64] fp32 (4KB)
#define SM_T     200768      // gT copy (8KB)
#define SMEM_BYTES 208960

__global__ void __launch_bounds__(512, 1)
agg_main(const float* __restrict__ x, const int* __restrict__ mask,
         float* __restrict__ out)
{
    extern __shared__ unsigned char sm[];
    const int t = threadIdx.x, w = t >> 5, lane = t & 31;
    const int b0 = blockIdx.x * 2;
    const uint32_t sb = smem_u32(sm);
    float* stage = (float*)(sm + SM_X);
    float* attb  = (float*)(sm + SM_ATT);
    float* sS    = (float*)(sm + SM_SS);
    const float* sT0 = (float*)(sm + SM_T);
    const float* sT1 = (float*)(sm + SM_T) + 128 * 8;

    // ---- prologue loads: group0 = x + T, group1 = B chunk0 ----
    const float* xp = x + (size_t)b0 * 8192;
    #pragma unroll
    for (int i = 0; i < 9; ++i) {
        int idx = t + i * 512;               // 0..4607
        if (idx < 4096)
            cp_async16(sb + SM_X + idx * 16, (const char*)xp + idx * 16);
        else
            cp_async16(sb + SM_T + (idx - 4096) * 16, (const char*)gT + (idx - 4096) * 16);
    }
    cp_commit();
    #pragma unroll
    for (int i = 0; i < 4; ++i) {
        int u = t + i * 512;                 // 0..2047
        int split = u >> 10, rem = u & 1023;
        cp_async16(sb + SM_B + u * 16, &gWimg[split][rem * 16]);   // chunk 0, buf 0
    }
    cp_commit();
    cp_wait<1>();        // x + T arrived
    __syncthreads();

    // ---- convert x -> A hi/lo tile images ----
    #pragma unroll
    for (int i = 0; i < 4; ++i) {
        int idx = t + i * 512;               // 2048 tasks of 8 elems
        int m = idx >> 4, k0 = (idx & 15) * 8;
        float4 v0 = *(float4*)(stage + m * 128 + k0);
        float4 v1 = *(float4*)(stage + m * 128 + k0 + 4);
        float v[8] = { v0.x, v0.y, v0.z, v0.w, v1.x, v1.y, v1.z, v1.w };
        __nv_bfloat16 h[8], l[8];
        #pragma unroll
        for (int j = 0; j < 8; ++j) {
            h[j] = __float2bfloat16(v[j]);
            l[j] = __float2bfloat16(v[j] - __bfloat162float(h[j]));
        }
        int mblk = m >> 4, rr = m & 15, kblk = k0 >> 4, kh = (k0 >> 3) & 1;
        uint32_t off = (uint32_t)mblk * 4096u + (uint32_t)kblk * 512u
                     + (((uint32_t)rr * 32u + (uint32_t)kh * 16u) ^ ((rr & 4) ? 16u : 0u));
        *(uint4*)(sm + SM_A + off) = make_uint4(pkbf2(h[0],h[1]), pkbf2(h[2],h[3]),
                                                pkbf2(h[4],h[5]), pkbf2(h[6],h[7]));
        *(uint4*)(sm + SM_A + 32768 + off) = make_uint4(pkbf2(l[0],l[1]), pkbf2(l[2],l[3]),
                                                        pkbf2(l[4],l[5]), pkbf2(l[6],l[7]));
    }

    // ---- attention logits: att[n][h] = leaky(x[0]@T0[:,h] + x[n]@T1[:,h]) ----
    float dotv[2]; int rr2[2], hh2[2];
    #pragma unroll
    for (int j = 0; j < 2; ++j) {
        int idx2 = t + j * 512;              // 1024 (row, h) tasks
        int r = idx2 >> 3, h = idx2 & 7;
        const float* xr = stage + r * 128;
        float acc = 0.f;
        #pragma unroll 4
        for (int k = 0; k < 128; k += 4) {
            float4 xv = *(float4*)(xr + k);
            acc += xv.x * sT1[(k + 0) * 8 + h];
            acc += xv.y * sT1[(k + 1) * 8 + h];
            acc += xv.z * sT1[(k + 2) * 8 + h];
            acc += xv.w * sT1[(k + 3) * 8 + h];
        }
        dotv[j] = acc; rr2[j] = r; hh2[j] = h;
    }
    if (t < 8) {    // src terms (row 0 of each batch) vs T0, head = t
        #pragma unroll
        for (int bb = 0; bb < 2; ++bb) {
            const float* xr = stage + bb * 64 * 128;
            float acc = 0.f;
            #pragma unroll 4
            for (int k = 0; k < 128; k += 4) {
                float4 xv = *(float4*)(xr + k);
                acc += xv.x * sT0[(k + 0) * 8 + t];
                acc += xv.y * sT0[(k + 1) * 8 + t];
                acc += xv.z * sT0[(k + 2) * 8 + t];
                acc += xv.w * sT0[(k + 3) * 8 + t];
            }
            sS[bb * 8 + t] = acc;
        }
    }
    __syncthreads();

    #pragma unroll
    for (int j = 0; j < 2; ++j) {
        int b = rr2[j] >> 6, n = rr2[j] & 63;
        float v = sS[b * 8 + hh2[j]] + dotv[j];
        v = (v >= 0.f) ? v : 0.2f * v;
        attb[(b * 8 + hh2[j]) * 64 + n] = v;
    }
    __syncthreads();

    // ---- softmax per (b, h): warp w -> (w>>3, w&7) ----
    {
        int b = w >> 3, h = w & 7;
        int m0 = mask[(b0 + b) * 64 + lane];
        int m1 = mask[(b0 + b) * 64 + lane + 32];
        float v0 = attb[(b * 8 + h) * 64 + lane]      + (m0 == 0 ? -1e9f : 0.f);
        float v1 = attb[(b * 8 + h) * 64 + lane + 32] + (m1 == 0 ? -1e9f : 0.f);
        float mx = fmaxf(v0, v1);
        #pragma unroll
        for (int o = 16; o > 0; o >>= 1) mx = fmaxf(mx, __shfl_xor_sync(0xffffffffu, mx, o));
        float e0 = __expf(v0 - mx), e1 = __expf(v1 - mx);
        float sum = e0 + e1;
        #pragma unroll
        for (int o = 16; o > 0; o >>= 1) sum += __shfl_xor_sync(0xffffffffu, sum, o);
        float inv = 1.f / sum;
        attb[(b * 8 + h) * 64 + lane]      = e0 * inv;
        attb[(b * 8 + h) * 64 + lane + 32] = e1 * inv;
    }

    // ---- mainloop: 8 N-chunks of 64 (chunk == head), double-buffered B ----
    const int mblk = w >> 1, nhalf = w & 1;
    // ldmatrix lane addressing
    const int ja = lane >> 3, ra = lane & 7;
    const int ml  = (ja & 1) * 8 + ra, kha = ja >> 1;
    const uint32_t arow = (((uint32_t)ml * 32u + (uint32_t)kha * 16u) ^ ((ml & 4) ? 16u : 0u));
    const uint32_t aad0 = sb + SM_A + (uint32_t)mblk * 4096u + arow;
    const int nbo = (ja >> 1), khb = ja & 1;
    const uint32_t brow = (((uint32_t)ra * 32u + (uint32_t)khb * 16u) ^ ((ra & 4) ? 16u : 0u));

    // epilogue lane mapping
    const int er = lane >> 2, ec = (lane & 3) * 2;
    const int gr0 = mblk * 16 + er, gr1 = gr0 + 8;
    const int bI0 = gr0 >> 6, ns0 = gr0 & 63;
    const int bI1 = gr1 >> 6, ns1 = gr1 & 63;

    for (int c = 0; c < 8; ++c) {
        __syncthreads();     // all warps done reading buf (c+1)&1 (chunk c-1)
        if (c < 7) {
            uint32_t dst = sb + SM_B + (uint32_t)((c + 1) & 1) * 32768u;
            #pragma unroll
            for (int i = 0; i < 4; ++i) {
                int u = t + i * 512;
                int split = u >> 10, rem = u & 1023;
                cp_async16(dst + u * 16, &gWimg[split][(c + 1) * 16384 + rem * 16]);
            }
            cp_commit();
            cp_wait<1>();
        } else {
            cp_wait<0>();
        }
        __syncthreads();     // B_c visible

        const uint32_t bbase = sb + SM_B + (uint32_t)(c & 1) * 32768u;
        float acc[16];
        #pragma unroll
        for (int i = 0; i < 16; ++i) acc[i] = 0.f;

        #pragma unroll
        for (int kblk = 0; kblk < 8; ++kblk) {
            uint32_t a0[4], a1[4];
            LDSM_X4(a0, aad0 + (uint32_t)kblk * 512u);
            LDSM_X4(a1, aad0 + 32768u + (uint32_t)kblk * 512u);
            #pragma unroll
            for (int ng = 0; ng < 2; ++ng) {
                uint32_t bad = bbase + (uint32_t)(nhalf * 4 + ng * 2 + nbo) * 2048u
                             + (uint32_t)kblk * 256u + brow;
                uint32_t bh[4], bl[4];
                LDSM_X4(bh, bad);
                mma16816(acc + ng * 8 + 0, a0, bh[0], bh[1]);   // x_hi * w_hi
                mma16816(acc + ng * 8 + 4, a0, bh[2], bh[3]);
                mma16816(acc + ng * 8 + 0, a1, bh[0], bh[1]);   // x_lo * w_hi
                mma16816(acc + ng * 8 + 4, a1, bh[2], bh[3]);
                LDSM_X4(bl, bad + 16384u);
                mma16816(acc + ng * 8 + 0, a0, bl[0], bl[1]);   // x_hi * w_lo
                mma16816(acc + ng * 8 + 4, a0, bl[2], bl[3]);
            }
        }

        // ---- epilogue: scale by aw[b][head=c][n], relu, store ----
        float sc0 = attb[(bI0 * 8 + c) * 64 + ns0];
        float sc1 = attb[(bI1 * 8 + c) * 64 + ns1];
        float* o0 = out + ((size_t)(b0 + bI0) * 64 + ns0) * 512 + c * 64 + nhalf * 32 + ec;
        float* o1 = out + ((size_t)(b0 + bI1) * 64 + ns1) * 512 + c * 64 + nhalf * 32 + ec;
        #pragma unroll
        for (int tt = 0; tt < 4; ++tt) {
            float2 lo = make_float2(fmaxf(acc[tt * 4 + 0] * sc0, 0.f),
                                    fmaxf(acc[tt * 4 + 1] * sc0, 0.f));
            float2 hi = make_float2(fmaxf(acc[tt * 4 + 2] * sc1, 0.f),
                                    fmaxf(acc[tt * 4 + 3] * sc1, 0.f));
            *(float2*)(o0 + tt * 8) = lo;
            *(float2*)(o1 + tt * 8) = hi;
        }
    }
}

// ---------------- launch ----------------
extern "C" void kernel_launch(void* const* d_in, const int* in_sizes, int n_in,
                              void* d_out, int out_size)
{
    const float* x    = (const float*)d_in[0];
    const float* Wlin = (const float*)d_in[1];
    const float* Watt = (const float*)d_in[2];
    const int*   mk   = (const int*)d_in[3];
    float*       out  = (float*)d_out;

    k_prepT<<<8, 256>>>(Wlin, Watt);
    k_prepW<<<256, 256>>>(Wlin);

    cudaFuncSetAttribute(agg_main, cudaFuncAttributeMaxDynamicSharedMemorySize, SMEM_BYTES);
    agg_main<<<NPAIR, 512, SMEM_BYTES>>>(x, mk, out);
}

// round 5
// speedup vs baseline: 2.2455x; 1.1082x over previous
#include <cuda_runtime.h>
#include <cuda_bf16.h>
#include <cstdint>

#define BATCH  4096
#define NPAIR  (BATCH / 2)

// ---------------- device-global staging (written by pre-kernel) ----------------
// gWimg[split][131072]: per split, layout [nblk 64][kblk 8][tile 256B],
//   tile = 8 n-rows x 16 k bf16, row nr at ((nr*32 + kh*16) ^ ((nr&4)?16:0)) + (k&7)*2
__device__ __align__(1024) unsigned char gWimg[2][131072];
// gT[half][f][h] = sum_c Wlin[f][c] * Watt[(half*512 + c)*8 + h]
__device__ __align__(16) float gT[2][128][8];

// ---------------- PTX helpers ----------------
__device__ __forceinline__ uint32_t smem_u32(const void* p) {
    uint32_t a;
    asm("{ .reg .u64 t; cvta.to.shared.u64 t, %1; cvt.u32.u64 %0, t; }" : "=r"(a) : "l"(p));
    return a;
}
__device__ __forceinline__ void cp_async16(uint32_t saddr, const void* g) {
    asm volatile("cp.async.cg.shared.global [%0], [%1], 16;" :: "r"(saddr), "l"(g));
}
__device__ __forceinline__ void cp_commit() { asm volatile("cp.async.commit_group;"); }
template<int N> __device__ __forceinline__ void cp_wait() {
    asm volatile("cp.async.wait_group %0;" :: "n"(N));
}

#define LDSM_X4(d, a)                                                             \
    asm volatile("ldmatrix.sync.aligned.m8n8.x4.shared.b16 {%0,%1,%2,%3}, [%4];"  \
        : "=r"((d)[0]), "=r"((d)[1]), "=r"((d)[2]), "=r"((d)[3]) : "r"(a))

__device__ __forceinline__ void mma16816(float* c, const uint32_t* a,
                                         uint32_t b0, uint32_t b1) {
    asm volatile("mma.sync.aligned.m16n8k16.row.col.f32.bf16.bf16.f32 "
        "{%0,%1,%2,%3}, {%4,%5,%6,%7}, {%8,%9}, {%0,%1,%2,%3};"
        : "+f"(c[0]), "+f"(c[1]), "+f"(c[2]), "+f"(c[3])
        : "r"(a[0]), "r"(a[1]), "r"(a[2]), "r"(a[3]), "r"(b0), "r"(b1));
}

__device__ __forceinline__ uint32_t pkbf2(__nv_bfloat16 a, __nv_bfloat16 b) {
    __nv_bfloat162 t; t.x = a; t.y = b;
    return *reinterpret_cast<uint32_t*>(&t);
}

// ---------------- fused pre-kernel ----------------
// blocks [0,32):  prepW — 8192 threads, each converts 8 k-values of one n column
// blocks [32,96): prepT — 16384 threads, 8 per output, shfl-reduced
__global__ void k_prep(const float* __restrict__ Wlin, const float* __restrict__ Watt) {
    int blk = blockIdx.x;
    if (blk < 32) {
        int t = blk * 256 + threadIdx.x;      // 0..8191
        int n = t & 511, ko = t >> 9;          // ko: 16 k-octs
        float v[8];
        #pragma unroll
        for (int j = 0; j < 8; ++j)
            v[j] = Wlin[(size_t)(ko * 8 + j) * 512 + n];
        __nv_bfloat16 h[8], l[8];
        #pragma unroll
        for (int j = 0; j < 8; ++j) {
            h[j] = __float2bfloat16(v[j]);
            l[j] = __float2bfloat16(v[j] - __bfloat162float(h[j]));
        }
        int nblk = n >> 3, nr = n & 7, kblk = ko >> 1, kh = ko & 1;
        uint32_t off = (uint32_t)nblk * 2048u + (uint32_t)kblk * 256u
                     + (((uint32_t)nr * 32u + (uint32_t)kh * 16u) ^ ((nr & 4) ? 16u : 0u));
        *(uint4*)(&gWimg[0][off]) = make_uint4(pkbf2(h[0],h[1]), pkbf2(h[2],h[3]),
                                               pkbf2(h[4],h[5]), pkbf2(h[6],h[7]));
        *(uint4*)(&gWimg[1][off]) = make_uint4(pkbf2(l[0],l[1]), pkbf2(l[2],l[3]),
                                               pkbf2(l[4],l[5]), pkbf2(l[6],l[7]));
    } else {
        int t = (blk - 32) * 256 + threadIdx.x;   // 0..16383
        int o = t >> 3, sub = t & 7;               // 2048 outputs, 8 threads each
        int half = o >> 10, f = (o >> 3) & 127, h = o & 7;
        const float* wl = Wlin + (size_t)f * 512;
        const float* wa = Watt + (size_t)half * 512 * 8 + h;
        float acc = 0.f;
        int c0 = sub * 64;
        #pragma unroll 8
        for (int c = c0; c < c0 + 64; ++c)
            acc += wl[c] * wa[(size_t)c * 8];
        #pragma unroll
        for (int off = 4; off > 0; off >>= 1)
            acc += __shfl_xor_sync(0xffffffffu, acc, off);
        if (sub == 0) gT[half][f][h] = acc;
    }
}

// ---------------- main kernel ----------------
// SMEM map (bytes):
//   A images:   [split][mblk 8][kblk 8][512B]  @ 0      (64KB; lo at +32768)
//   B ring:     3 x 32KB                        @ 65536 (96KB)
//     x fp32 stage [128][128] aliased onto buf0+buf1 during prologue
//   SS [2][8] fp32                              @ 163840
//   ATT [2][8][64] fp32                         @ 163904
//   T copy (8KB)                                @ 168000
#define SM_A     0
#define SM_B     65536
#define SM_SS    163840
#define SM_ATT   163904
#define SM_T     168000
#define SMEM_BYTES (SM_T + 8192)

__global__ void __launch_bounds__(512, 1)
agg_main(const float* __restrict__ x, const int* __restrict__ mask,
         float* __restrict__ out)
{
    extern __shared__ unsigned char sm[];
    const int t = threadIdx.x, w = t >> 5, lane = t & 31;
    const int b0 = blockIdx.x * 2;
    const uint32_t sb = smem_u32(sm);
    float* stage = (float*)(sm + SM_B);            // aliased on buf0+buf1
    float* attb  = (float*)(sm + SM_ATT);
    float* sS    = (float*)(sm + SM_SS);
    const float* sT0 = (float*)(sm + SM_T);
    const float* sT1 = (float*)(sm + SM_T) + 128 * 8;

    // ---- G0: x (64KB) + T (8KB) ----
    const float* xp = x + (size_t)b0 * 8192;
    #pragma unroll
    for (int i = 0; i < 8; ++i) {
        int idx = t + i * 512;
        cp_async16(sb + SM_B + idx * 16, (const char*)xp + idx * 16);
    }
    cp_async16(sb + SM_T + t * 16, (const char*)gT + t * 16);
    cp_commit();
    // ---- G1: chunk 0 -> buf2 (free region) ----
    #pragma unroll
    for (int i = 0; i < 4; ++i) {
        int u = t + i * 512;
        int split = u >> 10, rem = u & 1023;
        cp_async16(sb + SM_B + 65536u + u * 16, &gWimg[split][rem * 16]);
    }
    cp_commit();
    cp_wait<1>();       // x + T arrived (chunk0 may still be in flight)
    __syncthreads();

    // ---- convert x -> A hi/lo tile images ----
    #pragma unroll
    for (int i = 0; i < 4; ++i) {
        int idx = t + i * 512;               // 2048 tasks of 8 elems
        int m = idx >> 4, k0 = (idx & 15) * 8;
        float4 v0 = *(float4*)(stage + m * 128 + k0);
        float4 v1 = *(float4*)(stage + m * 128 + k0 + 4);
        float v[8] = { v0.x, v0.y, v0.z, v0.w, v1.x, v1.y, v1.z, v1.w };
        __nv_bfloat16 h[8], l[8];
        #pragma unroll
        for (int j = 0; j < 8; ++j) {
            h[j] = __float2bfloat16(v[j]);
            l[j] = __float2bfloat16(v[j] - __bfloat162float(h[j]));
        }
        int mblk = m >> 4, rr = m & 15, kblk = k0 >> 4, kh = (k0 >> 3) & 1;
        uint32_t off = (uint32_t)mblk * 4096u + (uint32_t)kblk * 512u
                     + (((uint32_t)rr * 32u + (uint32_t)kh * 16u) ^ ((rr & 4) ? 16u : 0u));
        *(uint4*)(sm + SM_A + off) = make_uint4(pkbf2(h[0],h[1]), pkbf2(h[2],h[3]),
                                                pkbf2(h[4],h[5]), pkbf2(h[6],h[7]));
        *(uint4*)(sm + SM_A + 32768 + off) = make_uint4(pkbf2(l[0],l[1]), pkbf2(l[2],l[3]),
                                                        pkbf2(l[4],l[5]), pkbf2(l[6],l[7]));
    }

    // ---- attention logits from stage (registers) ----
    float dotv[2]; int rr2[2], hh2[2];
    #pragma unroll
    for (int j = 0; j < 2; ++j) {
        int idx2 = t + j * 512;              // 1024 (row, h) tasks
        int r = idx2 >> 3, h = idx2 & 7;
        const float* xr = stage + r * 128;
        float acc = 0.f;
        #pragma unroll 4
        for (int k = 0; k < 128; k += 4) {
            float4 xv = *(float4*)(xr + k);
            acc += xv.x * sT1[(k + 0) * 8 + h];
            acc += xv.y * sT1[(k + 1) * 8 + h];
            acc += xv.z * sT1[(k + 2) * 8 + h];
            acc += xv.w * sT1[(k + 3) * 8 + h];
        }
        dotv[j] = acc; rr2[j] = r; hh2[j] = h;
    }
    float srcv[2];
    if (t < 8) {    // src terms (row 0 of each batch) vs T0, head = t
        #pragma unroll
        for (int bb = 0; bb < 2; ++bb) {
            const float* xr = stage + bb * 64 * 128;
            float acc = 0.f;
            #pragma unroll 4
            for (int k = 0; k < 128; k += 4) {
                float4 xv = *(float4*)(xr + k);
                acc += xv.x * sT0[(k + 0) * 8 + t];
                acc += xv.y * sT0[(k + 1) * 8 + t];
                acc += xv.z * sT0[(k + 2) * 8 + t];
                acc += xv.w * sT0[(k + 3) * 8 + t];
            }
            srcv[bb] = acc;
        }
    }
    __syncthreads();    // stage fully read; conversion visible
    if (t < 8) { sS[t] = srcv[0]; sS[8 + t] = srcv[1]; }

    // ---- issue chunk1 -> buf0 (stage region now dead) ----
    #pragma unroll
    for (int i = 0; i < 4; ++i) {
        int u = t + i * 512;
        int split = u >> 10, rem = u & 1023;
        cp_async16(sb + SM_B + u * 16, &gWimg[split][16384 + rem * 16]);
    }
    cp_commit();

    // ---- hoist A fragments into registers (chunk-invariant) ----
    const int mblk = w >> 1, nhalf = w & 1;
    const int ja = lane >> 3, ra = lane & 7;
    const int ml  = (ja & 1) * 8 + ra, kha = ja >> 1;
    const uint32_t arow = (((uint32_t)ml * 32u + (uint32_t)kha * 16u) ^ ((ml & 4) ? 16u : 0u));
    const uint32_t aad0 = sb + SM_A + (uint32_t)mblk * 4096u + arow;
    uint32_t a0f[8][4], a1f[8][4];
    #pragma unroll
    for (int kblk = 0; kblk < 8; ++kblk) {
        LDSM_X4(a0f[kblk], aad0 + (uint32_t)kblk * 512u);
        LDSM_X4(a1f[kblk], aad0 + 32768u + (uint32_t)kblk * 512u);
    }
    __syncthreads();    // sS visible

    // ---- logits -> attb ----
    #pragma unroll
    for (int j = 0; j < 2; ++j) {
        int b = rr2[j] >> 6, n = rr2[j] & 63;
        float v = sS[b * 8 + hh2[j]] + dotv[j];
        v = (v >= 0.f) ? v : 0.2f * v;
        attb[(b * 8 + hh2[j]) * 64 + n] = v;
    }
    __syncthreads();    // attb logits visible

    // ---- softmax per (b, h): warp w -> (w>>3, w&7) ----
    {
        int b = w >> 3, h = w & 7;
        int m0 = mask[(b0 + b) * 64 + lane];
        int m1 = mask[(b0 + b) * 64 + lane + 32];
        float v0 = attb[(b * 8 + h) * 64 + lane]      + (m0 == 0 ? -1e9f : 0.f);
        float v1 = attb[(b * 8 + h) * 64 + lane + 32] + (m1 == 0 ? -1e9f : 0.f);
        float mx = fmaxf(v0, v1);
        #pragma unroll
        for (int o = 16; o > 0; o >>= 1) mx = fmaxf(mx, __shfl_xor_sync(0xffffffffu, mx, o));
        float e0 = __expf(v0 - mx), e1 = __expf(v1 - mx);
        float sum = e0 + e1;
        #pragma unroll
        for (int o = 16; o > 0; o >>= 1) sum += __shfl_xor_sync(0xffffffffu, sum, o);
        float inv = 1.f / sum;
        attb[(b * 8 + h) * 64 + lane]      = e0 * inv;
        attb[(b * 8 + h) * 64 + lane + 32] = e1 * inv;
    }

    // ---- B ldmatrix addressing + epilogue lane mapping ----
    const int nbo = (ja >> 1), khb = ja & 1;
    const uint32_t brow = (((uint32_t)ra * 32u + (uint32_t)khb * 16u) ^ ((ra & 4) ? 16u : 0u));
    const int er = lane >> 2, ec = (lane & 3) * 2;
    const int gr0 = mblk * 16 + er, gr1 = gr0 + 8;
    const int bI0 = gr0 >> 6, ns0 = gr0 & 63;
    const int bI1 = gr1 >> 6, ns1 = gr1 & 63;

    // ---- mainloop: 8 N-chunks (chunk == head), 3-stage B ring ----
    // chunk m lives in buf (m+2)%3; chunk c+2 issued at iter c into buf (c+1)%3
    for (int c = 0; c < 8; ++c) {
        if (c < 7) cp_wait<1>(); else cp_wait<0>();   // chunk c arrived
        __syncthreads();                               // visibility + ring protection
        if (c + 2 <= 7) {
            uint32_t dst = sb + SM_B + (uint32_t)((c + 1) % 3) * 32768u;
            #pragma unroll
            for (int i = 0; i < 4; ++i) {
                int u = t + i * 512;
                int split = u >> 10, rem = u & 1023;
                cp_async16(dst + u * 16, &gWimg[split][(c + 2) * 16384 + rem * 16]);
            }
            cp_commit();
        }

        const uint32_t bbase = sb + SM_B + (uint32_t)((c + 2) % 3) * 32768u;
        float acc[16];
        #pragma unroll
        for (int i = 0; i < 16; ++i) acc[i] = 0.f;

        #pragma unroll
        for (int kblk = 0; kblk < 8; ++kblk) {
            #pragma unroll
            for (int ng = 0; ng < 2; ++ng) {
                uint32_t bad = bbase + (uint32_t)(nhalf * 4 + ng * 2 + nbo) * 2048u
                             + (uint32_t)kblk * 256u + brow;
                uint32_t bh[4], bl[4];
                LDSM_X4(bh, bad);
                LDSM_X4(bl, bad + 16384u);
                mma16816(acc + ng * 8 + 0, a0f[kblk], bh[0], bh[1]);  // x_hi w_hi
                mma16816(acc + ng * 8 + 4, a0f[kblk], bh[2], bh[3]);
                mma16816(acc + ng * 8 + 0, a1f[kblk], bh[0], bh[1]);  // x_lo w_hi
                mma16816(acc + ng * 8 + 4, a1f[kblk], bh[2], bh[3]);
                mma16816(acc + ng * 8 + 0, a0f[kblk], bl[0], bl[1]);  // x_hi w_lo
                mma16816(acc + ng * 8 + 4, a0f[kblk], bl[2], bl[3]);
            }
        }

        // ---- epilogue: scale by aw[b][head=c][n], relu, store ----
        float sc0 = attb[(bI0 * 8 + c) * 64 + ns0];
        float sc1 = attb[(bI1 * 8 + c) * 64 + ns1];
        float* o0 = out + ((size_t)(b0 + bI0) * 64 + ns0) * 512 + c * 64 + nhalf * 32 + ec;
        float* o1 = out + ((size_t)(b0 + bI1) * 64 + ns1) * 512 + c * 64 + nhalf * 32 + ec;
        #pragma unroll
        for (int tt = 0; tt < 4; ++tt) {
            float2 lo = make_float2(fmaxf(acc[tt * 4 + 0] * sc0, 0.f),
                                    fmaxf(acc[tt * 4 + 1] * sc0, 0.f));
            float2 hi = make_float2(fmaxf(acc[tt * 4 + 2] * sc1, 0.f),
                                    fmaxf(acc[tt * 4 + 3] * sc1, 0.f));
            *(float2*)(o0 + tt * 8) = lo;
            *(float2*)(o1 + tt * 8) = hi;
        }
    }
}

// ---------------- launch ----------------
extern "C" void kernel_launch(void* const* d_in, const int* in_sizes, int n_in,
                              void* d_out, int out_size)
{
    const float* x    = (const float*)d_in[0];
    const float* Wlin = (const float*)d_in[1];
    const float* Watt = (const float*)d_in[2];
    const int*   mk   = (const int*)d_in[3];
    float*       out  = (float*)d_out;

    k_prep<<<96, 256>>>(Wlin, Watt);

    cudaFuncSetAttribute(agg_main, cudaFuncAttributeMaxDynamicSharedMemorySize, SMEM_BYTES);
    agg_main<<<NPAIR, 512, SMEM_BYTES>>>(x, mk, out);
}

// round 6
// speedup vs baseline: 2.2901x; 1.0199x over previous
#include <cuda_runtime.h>
#include <cuda_bf16.h>
#include <cstdint>

#define BATCH  4096
#define NPAIR  (BATCH / 2)

// ---------------- device-global staging (written by pre-kernel) ----------------
// gWimg[split][131072]: per split, layout [nblk 64][kblk 8][tile 256B],
//   tile = 8 n-slots x 16 k bf16, slot nr at ((nr*32 + kh*16) ^ ((nr&4)?16:0)) + (k&7)*2
//   N-PERMUTATION: global col n -> (nblk, slot):
//     chunk=n>>6, cc=n&63, nhalf=cc>>5, w32=cc&31, j=w32>>3, g=(w32>>1)&3, r=w32&1
//     nblk = chunk*8 + nhalf*4 + g ; slot = 2j + r
//   => thread j of each mma row owns global cols 8j..8j+7 (contiguous stores).
__device__ __align__(1024) unsigned char gWimg[2][131072];
// gT[half][f][h] = sum_c Wlin[f][c] * Watt[(half*512 + c)*8 + h]
__device__ __align__(16) float gT[2][128][8];

// ---------------- PTX helpers ----------------
__device__ __forceinline__ uint32_t smem_u32(const void* p) {
    uint32_t a;
    asm("{ .reg .u64 t; cvta.to.shared.u64 t, %1; cvt.u32.u64 %0, t; }" : "=r"(a) : "l"(p));
    return a;
}
__device__ __forceinline__ void cp_async16(uint32_t saddr, const void* g) {
    asm volatile("cp.async.cg.shared.global [%0], [%1], 16;" :: "r"(saddr), "l"(g));
}
__device__ __forceinline__ void cp_commit() { asm volatile("cp.async.commit_group;"); }
template<int N> __device__ __forceinline__ void cp_wait() {
    asm volatile("cp.async.wait_group %0;" :: "n"(N));
}

#define LDSM_X4(d, a)                                                             \
    asm volatile("ldmatrix.sync.aligned.m8n8.x4.shared.b16 {%0,%1,%2,%3}, [%4];"  \
        : "=r"((d)[0]), "=r"((d)[1]), "=r"((d)[2]), "=r"((d)[3]) : "r"(a))

__device__ __forceinline__ void mma16816(float* c, const uint32_t* a,
                                         uint32_t b0, uint32_t b1) {
    asm volatile("mma.sync.aligned.m16n8k16.row.col.f32.bf16.bf16.f32 "
        "{%0,%1,%2,%3}, {%4,%5,%6,%7}, {%8,%9}, {%0,%1,%2,%3};"
        : "+f"(c[0]), "+f"(c[1]), "+f"(c[2]), "+f"(c[3])
        : "r"(a[0]), "r"(a[1]), "r"(a[2]), "r"(a[3]), "r"(b0), "r"(b1));
}

__device__ __forceinline__ uint32_t pkbf2(__nv_bfloat16 a, __nv_bfloat16 b) {
    __nv_bfloat162 t; t.x = a; t.y = b;
    return *reinterpret_cast<uint32_t*>(&t);
}

// ---------------- fused pre-kernel ----------------
__global__ void k_prep(const float* __restrict__ Wlin, const float* __restrict__ Watt) {
    int blk = blockIdx.x;
    if (blk < 32) {
        int t = blk * 256 + threadIdx.x;      // 0..8191
        int n = t & 511, ko = t >> 9;          // ko: 16 k-octs
        float v[8];
        #pragma unroll
        for (int j = 0; j < 8; ++j)
            v[j] = Wlin[(size_t)(ko * 8 + j) * 512 + n];
        __nv_bfloat16 h[8], l[8];
        #pragma unroll
        for (int j = 0; j < 8; ++j) {
            h[j] = __float2bfloat16(v[j]);
            l[j] = __float2bfloat16(v[j] - __bfloat162float(h[j]));
        }
        // permuted (nblk, slot)
        int chunk = n >> 6, cc = n & 63, nhalf = cc >> 5, w32 = cc & 31;
        int jj = w32 >> 3, g = (w32 >> 1) & 3, r = w32 & 1;
        int nblk = chunk * 8 + nhalf * 4 + g;
        int nr = jj * 2 + r;
        int kblk = ko >> 1, kh = ko & 1;
        uint32_t off = (uint32_t)nblk * 2048u + (uint32_t)kblk * 256u
                     + (((uint32_t)nr * 32u + (uint32_t)kh * 16u) ^ ((nr & 4) ? 16u : 0u));
        *(uint4*)(&gWimg[0][off]) = make_uint4(pkbf2(h[0],h[1]), pkbf2(h[2],h[3]),
                                               pkbf2(h[4],h[5]), pkbf2(h[6],h[7]));
        *(uint4*)(&gWimg[1][off]) = make_uint4(pkbf2(l[0],l[1]), pkbf2(l[2],l[3]),
                                               pkbf2(l[4],l[5]), pkbf2(l[6],l[7]));
    } else {
        int t = (blk - 32) * 256 + threadIdx.x;   // 0..16383
        int o = t >> 3, sub = t & 7;               // 2048 outputs, 8 threads each
        int half = o >> 10, f = (o >> 3) & 127, h = o & 7;
        const float* wl = Wlin + (size_t)f * 512;
        const float* wa = Watt + (size_t)half * 512 * 8 + h;
        float acc = 0.f;
        int c0 = sub * 64;
        #pragma unroll 8
        for (int c = c0; c < c0 + 64; ++c)
            acc += wl[c] * wa[(size_t)c * 8];
        #pragma unroll
        for (int off = 4; off > 0; off >>= 1)
            acc += __shfl_xor_sync(0xffffffffu, acc, off);
        if (sub == 0) gT[half][f][h] = acc;
    }
}

// ---------------- main kernel ----------------
#define SM_A     0
#define SM_B     65536
#define SM_SS    163840
#define SM_ATT   163904
#define SM_T     168000
#define SMEM_BYTES (SM_T + 8192)

__global__ void __launch_bounds__(512, 1)
agg_main(const float* __restrict__ x, const int* __restrict__ mask,
         float* __restrict__ out)
{
    extern __shared__ unsigned char sm[];
    const int t = threadIdx.x, w = t >> 5, lane = t & 31;
    const int b0 = blockIdx.x * 2;
    const uint32_t sb = smem_u32(sm);
    float* stage = (float*)(sm + SM_B);            // aliased on buf0+buf1
    float* attb  = (float*)(sm + SM_ATT);
    float* sS    = (float*)(sm + SM_SS);
    const float* sT0 = (float*)(sm + SM_T);
    const float* sT1 = (float*)(sm + SM_T) + 128 * 8;

    // ---- G0: x (64KB) + T (8KB) ----
    const float* xp = x + (size_t)b0 * 8192;
    #pragma unroll
    for (int i = 0; i < 8; ++i) {
        int idx = t + i * 512;
        cp_async16(sb + SM_B + idx * 16, (const char*)xp + idx * 16);
    }
    cp_async16(sb + SM_T + t * 16, (const char*)gT + t * 16);
    cp_commit();
    // ---- G1: chunk 0 -> buf2 ----
    #pragma unroll
    for (int i = 0; i < 4; ++i) {
        int u = t + i * 512;
        int split = u >> 10, rem = u & 1023;
        cp_async16(sb + SM_B + 65536u + u * 16, &gWimg[split][rem * 16]);
    }
    cp_commit();
    cp_wait<1>();       // x + T arrived
    __syncthreads();

    // ---- convert x -> A hi/lo tile images ----
    #pragma unroll
    for (int i = 0; i < 4; ++i) {
        int idx = t + i * 512;
        int m = idx >> 4, k0 = (idx & 15) * 8;
        float4 v0 = *(float4*)(stage + m * 128 + k0);
        float4 v1 = *(float4*)(stage + m * 128 + k0 + 4);
        float v[8] = { v0.x, v0.y, v0.z, v0.w, v1.x, v1.y, v1.z, v1.w };
        __nv_bfloat16 h[8], l[8];
        #pragma unroll
        for (int j = 0; j < 8; ++j) {
            h[j] = __float2bfloat16(v[j]);
            l[j] = __float2bfloat16(v[j] - __bfloat162float(h[j]));
        }
        int mblk = m >> 4, rr = m & 15, kblk = k0 >> 4, kh = (k0 >> 3) & 1;
        uint32_t off = (uint32_t)mblk * 4096u + (uint32_t)kblk * 512u
                     + (((uint32_t)rr * 32u + (uint32_t)kh * 16u) ^ ((rr & 4) ? 16u : 0u));
        *(uint4*)(sm + SM_A + off) = make_uint4(pkbf2(h[0],h[1]), pkbf2(h[2],h[3]),
                                                pkbf2(h[4],h[5]), pkbf2(h[6],h[7]));
        *(uint4*)(sm + SM_A + 32768 + off) = make_uint4(pkbf2(l[0],l[1]), pkbf2(l[2],l[3]),
                                                        pkbf2(l[4],l[5]), pkbf2(l[6],l[7]));
    }

    // ---- attention logits from stage ----
    float dotv[2]; int rr2[2], hh2[2];
    #pragma unroll
    for (int j = 0; j < 2; ++j) {
        int idx2 = t + j * 512;
        int r = idx2 >> 3, h = idx2 & 7;
        const float* xr = stage + r * 128;
        float acc = 0.f;
        #pragma unroll 4
        for (int k = 0; k < 128; k += 4) {
            float4 xv = *(float4*)(xr + k);
            acc += xv.x * sT1[(k + 0) * 8 + h];
            acc += xv.y * sT1[(k + 1) * 8 + h];
            acc += xv.z * sT1[(k + 2) * 8 + h];
            acc += xv.w * sT1[(k + 3) * 8 + h];
        }
        dotv[j] = acc; rr2[j] = r; hh2[j] = h;
    }
    float srcv[2];
    if (t < 8) {
        #pragma unroll
        for (int bb = 0; bb < 2; ++bb) {
            const float* xr = stage + bb * 64 * 128;
            float acc = 0.f;
            #pragma unroll 4
            for (int k = 0; k < 128; k += 4) {
                float4 xv = *(float4*)(xr + k);
                acc += xv.x * sT0[(k + 0) * 8 + t];
                acc += xv.y * sT0[(k + 1) * 8 + t];
                acc += xv.z * sT0[(k + 2) * 8 + t];
                acc += xv.w * sT0[(k + 3) * 8 + t];
            }
            srcv[bb] = acc;
        }
    }
    __syncthreads();    // stage fully read
    if (t < 8) { sS[t] = srcv[0]; sS[8 + t] = srcv[1]; }

    // ---- issue chunk1 -> buf0 (stage dead) ----
    #pragma unroll
    for (int i = 0; i < 4; ++i) {
        int u = t + i * 512;
        int split = u >> 10, rem = u & 1023;
        cp_async16(sb + SM_B + u * 16, &gWimg[split][16384 + rem * 16]);
    }
    cp_commit();

    // ---- hoist A fragments (chunk-invariant) ----
    const int mblk = w >> 1, nhalf = w & 1;
    const int ja = lane >> 3, ra = lane & 7;
    const int ml  = (ja & 1) * 8 + ra, kha = ja >> 1;
    const uint32_t arow = (((uint32_t)ml * 32u + (uint32_t)kha * 16u) ^ ((ml & 4) ? 16u : 0u));
    const uint32_t aad0 = sb + SM_A + (uint32_t)mblk * 4096u + arow;
    uint32_t a0f[8][4], a1f[8][4];
    #pragma unroll
    for (int kblk = 0; kblk < 8; ++kblk) {
        LDSM_X4(a0f[kblk], aad0 + (uint32_t)kblk * 512u);
        LDSM_X4(a1f[kblk], aad0 + 32768u + (uint32_t)kblk * 512u);
    }
    __syncthreads();    // sS visible

    // ---- logits -> attb ----
    #pragma unroll
    for (int j = 0; j < 2; ++j) {
        int b = rr2[j] >> 6, n = rr2[j] & 63;
        float v = sS[b * 8 + hh2[j]] + dotv[j];
        v = (v >= 0.f) ? v : 0.2f * v;
        attb[(b * 8 + hh2[j]) * 64 + n] = v;
    }
    __syncthreads();

    // ---- softmax per (b, h): warp w -> (w>>3, w&7) ----
    {
        int b = w >> 3, h = w & 7;
        int m0 = mask[(b0 + b) * 64 + lane];
        int m1 = mask[(b0 + b) * 64 + lane + 32];
        float v0 = attb[(b * 8 + h) * 64 + lane]      + (m0 == 0 ? -1e9f : 0.f);
        float v1 = attb[(b * 8 + h) * 64 + lane + 32] + (m1 == 0 ? -1e9f : 0.f);
        float mx = fmaxf(v0, v1);
        #pragma unroll
        for (int o = 16; o > 0; o >>= 1) mx = fmaxf(mx, __shfl_xor_sync(0xffffffffu, mx, o));
        float e0 = __expf(v0 - mx), e1 = __expf(v1 - mx);
        float sum = e0 + e1;
        #pragma unroll
        for (int o = 16; o > 0; o >>= 1) sum += __shfl_xor_sync(0xffffffffu, sum, o);
        float inv = 1.f / sum;
        attb[(b * 8 + h) * 64 + lane]      = e0 * inv;
        attb[(b * 8 + h) * 64 + lane + 32] = e1 * inv;
    }

    // ---- B addressing + epilogue lane mapping (permuted columns) ----
    const int nbo = (ja >> 1), khb = ja & 1;
    const uint32_t brow = (((uint32_t)ra * 32u + (uint32_t)khb * 16u) ^ ((ra & 4) ? 16u : 0u));
    const int er = lane >> 2, jj = lane & 3;       // jj: contiguous 8-col group owner
    const int gr0 = mblk * 16 + er, gr1 = gr0 + 8;
    const int bI0 = gr0 >> 6, ns0 = gr0 & 63;
    const int bI1 = gr1 >> 6, ns1 = gr1 & 63;
    float* ob0 = out + ((size_t)(b0 + bI0) * 64 + ns0) * 512 + nhalf * 32 + jj * 8;
    float* ob1 = out + ((size_t)(b0 + bI1) * 64 + ns1) * 512 + nhalf * 32 + jj * 8;

    // ---- mainloop: 8 N-chunks (chunk == head), 3-stage B ring ----
    for (int c = 0; c < 8; ++c) {
        if (c < 7) cp_wait<1>(); else cp_wait<0>();
        __syncthreads();
        if (c + 2 <= 7) {
            uint32_t dst = sb + SM_B + (uint32_t)((c + 1) % 3) * 32768u;
            #pragma unroll
            for (int i = 0; i < 4; ++i) {
                int u = t + i * 512;
                int split = u >> 10, rem = u & 1023;
                cp_async16(dst + u * 16, &gWimg[split][(c + 2) * 16384 + rem * 16]);
            }
            cp_commit();
        }

        const uint32_t bbase = sb + SM_B + (uint32_t)((c + 2) % 3) * 32768u;
        float acc[16];
        #pragma unroll
        for (int i = 0; i < 16; ++i) acc[i] = 0.f;

        // depth-1 pipelined B stream: flat iter i = kblk*2 + ng
        uint32_t bh[2][4], bl[2][4];
        {
            uint32_t bad = bbase + (uint32_t)(nhalf * 4 + nbo) * 2048u + brow;
            LDSM_X4(bh[0], bad);
            LDSM_X4(bl[0], bad + 16384u);
        }
        #pragma unroll
        for (int i = 0; i < 16; ++i) {
            const int cur = i & 1, nxt = cur ^ 1;
            if (i < 15) {
                int kn = i + 1;
                uint32_t bad = bbase
                    + (uint32_t)(nhalf * 4 + (kn & 1) * 2 + nbo) * 2048u
                    + (uint32_t)(kn >> 1) * 256u + brow;
                LDSM_X4(bh[nxt], bad);
                LDSM_X4(bl[nxt], bad + 16384u);
            }
            const int kblk = i >> 1, go = (i & 1) * 8;
            mma16816(acc + go + 0, a0f[kblk], bh[cur][0], bh[cur][1]);  // x_hi w_hi
            mma16816(acc + go + 4, a0f[kblk], bh[cur][2], bh[cur][3]);
            mma16816(acc + go + 0, a1f[kblk], bh[cur][0], bh[cur][1]);  // x_lo w_hi
            mma16816(acc + go + 4, a1f[kblk], bh[cur][2], bh[cur][3]);
            mma16816(acc + go + 0, a0f[kblk], bl[cur][0], bl[cur][1]);  // x_hi w_lo
            mma16816(acc + go + 4, a0f[kblk], bl[cur][2], bl[cur][3]);
        }

        // ---- epilogue: permuted cols => each thread owns 8 contiguous floats/row ----
        // tile g (0..3) <-> acc[(g>>1)*8 + (g&1)*4 + ...]; col 8*jj + 2g + r
        float sc0 = attb[(bI0 * 8 + c) * 64 + ns0];
        float sc1 = attb[(bI1 * 8 + c) * 64 + ns1];
        float* o0 = ob0 + c * 64;
        float* o1 = ob1 + c * 64;
        float4 v00 = make_float4(fmaxf(acc[0]  * sc0, 0.f), fmaxf(acc[1]  * sc0, 0.f),
                                 fmaxf(acc[4]  * sc0, 0.f), fmaxf(acc[5]  * sc0, 0.f));
        float4 v01 = make_float4(fmaxf(acc[8]  * sc0, 0.f), fmaxf(acc[9]  * sc0, 0.f),
                                 fmaxf(acc[12] * sc0, 0.f), fmaxf(acc[13] * sc0, 0.f));
        float4 v10 = make_float4(fmaxf(acc[2]  * sc1, 0.f), fmaxf(acc[3]  * sc1, 0.f),
                                 fmaxf(acc[6]  * sc1, 0.f), fmaxf(acc[7]  * sc1, 0.f));
        float4 v11 = make_float4(fmaxf(acc[10] * sc1, 0.f), fmaxf(acc[11] * sc1, 0.f),
                                 fmaxf(acc[14] * sc1, 0.f), fmaxf(acc[15] * sc1, 0.f));
        *(float4*)(o0)     = v00;
        *(float4*)(o0 + 4) = v01;
        *(float4*)(o1)     = v10;
        *(float4*)(o1 + 4) = v11;
    }
}

// ---------------- launch ----------------
extern "C" void kernel_launch(void* const* d_in, const int* in_sizes, int n_in,
                              void* d_out, int out_size)
{
    const float* x    = (const float*)d_in[0];
    const float* Wlin = (const float*)d_in[1];
    const float* Watt = (const float*)d_in[2];
    const int*   mk   = (const int*)d_in[3];
    float*       out  = (float*)d_out;

    k_prep<<<96, 256>>>(Wlin, Watt);

    cudaFuncSetAttribute(agg_main, cudaFuncAttributeMaxDynamicSharedMemorySize, SMEM_BYTES);
    agg_main<<<NPAIR, 512, SMEM_BYTES>>>(x, mk, out);
}

// round 7
// speedup vs baseline: 2.7302x; 1.1922x over previous
#include <cuda_runtime.h>
#include <cuda_bf16.h>
#include <cstdint>

#define BATCH  4096

// ---------------- device-global staging (written by pre-kernel) ----------------
// gWimg[split][131072]: per split, [chunk 8][nblk 8][kblk 8][tile 256B]
//   tile = 8 n-slots x 16 k bf16, slot nr at ((nr*32 + kh*16) ^ ((nr&4)?16:0)) + (k&7)*2
//   N-permutation (contiguous epilogue stores):
//     chunk=n>>6, cc=n&63, nhalf=cc>>5, w32=cc&31, j=w32>>3, g=(w32>>1)&3, r=w32&1
//     nblk = nhalf*4 + g ; slot = 2j + r
__device__ __align__(1024) unsigned char gWimg[2][131072];
// gT[half][f][h] = sum_c Wlin[f][c] * Watt[(half*512 + c)*8 + h]
__device__ __align__(16) float gT[2][128][8];

// ---------------- PTX helpers ----------------
__device__ __forceinline__ uint32_t smem_u32(const void* p) {
    uint32_t a;
    asm("{ .reg .u64 t; cvta.to.shared.u64 t, %1; cvt.u32.u64 %0, t; }" : "=r"(a) : "l"(p));
    return a;
}
__device__ __forceinline__ void cp_async16(uint32_t saddr, const void* g) {
    asm volatile("cp.async.cg.shared.global [%0], [%1], 16;" :: "r"(saddr), "l"(g));
}
__device__ __forceinline__ void cp_commit() { asm volatile("cp.async.commit_group;"); }
template<int N> __device__ __forceinline__ void cp_wait() {
    asm volatile("cp.async.wait_group %0;" :: "n"(N));
}

#define LDSM_X4(d, a)                                                             \
    asm volatile("ldmatrix.sync.aligned.m8n8.x4.shared.b16 {%0,%1,%2,%3}, [%4];"  \
        : "=r"((d)[0]), "=r"((d)[1]), "=r"((d)[2]), "=r"((d)[3]) : "r"(a))

__device__ __forceinline__ void mma16816(float* c, const uint32_t* a,
                                         uint32_t b0, uint32_t b1) {
    asm volatile("mma.sync.aligned.m16n8k16.row.col.f32.bf16.bf16.f32 "
        "{%0,%1,%2,%3}, {%4,%5,%6,%7}, {%8,%9}, {%0,%1,%2,%3};"
        : "+f"(c[0]), "+f"(c[1]), "+f"(c[2]), "+f"(c[3])
        : "r"(a[0]), "r"(a[1]), "r"(a[2]), "r"(a[3]), "r"(b0), "r"(b1));
}

__device__ __forceinline__ uint32_t pkbf2(__nv_bfloat16 a, __nv_bfloat16 b) {
    __nv_bfloat162 t; t.x = a; t.y = b;
    return *reinterpret_cast<uint32_t*>(&t);
}

// ---------------- fused pre-kernel ----------------
__global__ void k_prep(const float* __restrict__ Wlin, const float* __restrict__ Watt) {
    int blk = blockIdx.x;
    if (blk < 32) {
        int t = blk * 256 + threadIdx.x;      // 0..8191
        int n = t & 511, ko = t >> 9;          // ko: 16 k-octs
        float v[8];
        #pragma unroll
        for (int j = 0; j < 8; ++j)
            v[j] = Wlin[(size_t)(ko * 8 + j) * 512 + n];
        __nv_bfloat16 h[8], l[8];
        #pragma unroll
        for (int j = 0; j < 8; ++j) {
            h[j] = __float2bfloat16(v[j]);
            l[j] = __float2bfloat16(v[j] - __bfloat162float(h[j]));
        }
        int chunk = n >> 6, cc = n & 63, nhalf = cc >> 5, w32 = cc & 31;
        int jj = w32 >> 3, g = (w32 >> 1) & 3, r = w32 & 1;
        int nblk = chunk * 8 + nhalf * 4 + g;
        int nr = jj * 2 + r;
        int kblk = ko >> 1, kh = ko & 1;
        uint32_t off = (uint32_t)nblk * 2048u + (uint32_t)kblk * 256u
                     + (((uint32_t)nr * 32u + (uint32_t)kh * 16u) ^ ((nr & 4) ? 16u : 0u));
        *(uint4*)(&gWimg[0][off]) = make_uint4(pkbf2(h[0],h[1]), pkbf2(h[2],h[3]),
                                               pkbf2(h[4],h[5]), pkbf2(h[6],h[7]));
        *(uint4*)(&gWimg[1][off]) = make_uint4(pkbf2(l[0],l[1]), pkbf2(l[2],l[3]),
                                               pkbf2(l[4],l[5]), pkbf2(l[6],l[7]));
    } else {
        int t = (blk - 32) * 256 + threadIdx.x;   // 0..16383
        int o = t >> 3, sub = t & 7;               // 2048 outputs, 8 threads each
        int half = o >> 10, f = (o >> 3) & 127, h = o & 7;
        const float* wl = Wlin + (size_t)f * 512;
        const float* wa = Watt + (size_t)half * 512 * 8 + h;
        float acc = 0.f;
        int c0 = sub * 64;
        #pragma unroll 8
        for (int c = c0; c < c0 + 64; ++c)
            acc += wl[c] * wa[(size_t)c * 8];
        #pragma unroll
        for (int off = 4; off > 0; off >>= 1)
            acc += __shfl_xor_sync(0xffffffffu, acc, off);
        if (sub == 0) gT[half][f][h] = acc;
    }
}

// ---------------- main kernel: 256 threads, 1 batch, 2 CTAs/SM ----------------
// SMEM (bytes): A images [split][mblk4][kblk8][512B] @0 (32KB, lo at +16384)
//               B double buffer 2 x 32KB @32768 (x fp32 stage [64][128] aliased on buf1)
//               SS[8] @98304 ; ATT[8][64] @98368 ; T copy @100416 (8KB)
#define SM_A     0
#define SM_B     32768
#define SM_SS    98304
#define SM_ATT   98368
#define SM_T     100416
#define SMEM_BYTES (SM_T + 8192)

__global__ void __launch_bounds__(256, 2)
agg_main(const float* __restrict__ x, const int* __restrict__ mask,
         float* __restrict__ out)
{
    extern __shared__ unsigned char sm[];
    const int t = threadIdx.x, w = t >> 5, lane = t & 31;
    const int b = blockIdx.x;
    const uint32_t sb = smem_u32(sm);
    float* stage = (float*)(sm + SM_B + 32768);    // x stage aliased on B buf1
    float* attb  = (float*)(sm + SM_ATT);
    float* sS    = (float*)(sm + SM_SS);
    const float* sT0 = (float*)(sm + SM_T);
    const float* sT1 = (float*)(sm + SM_T) + 128 * 8;

    // ---- G0: x (32KB) + T (8KB) ----
    const float* xp = x + (size_t)b * 8192;
    #pragma unroll
    for (int i = 0; i < 8; ++i) {
        int idx = t + i * 256;                      // 0..2047
        cp_async16(sb + SM_B + 32768u + idx * 16, (const char*)xp + idx * 16);
    }
    #pragma unroll
    for (int i = 0; i < 2; ++i) {
        int idx = t + i * 256;                      // 0..511
        cp_async16(sb + SM_T + idx * 16, (const char*)gT + idx * 16);
    }
    cp_commit();
    // ---- G1: chunk 0 -> buf0 ----
    #pragma unroll
    for (int i = 0; i < 8; ++i) {
        int u = t + i * 256;                        // 0..2047
        int split = u >> 10, rem = u & 1023;
        cp_async16(sb + SM_B + u * 16, &gWimg[split][rem * 16]);
    }
    cp_commit();
    cp_wait<1>();       // x + T arrived (chunk0 may still be in flight)
    __syncthreads();

    // ---- convert x -> A hi/lo tile images (1024 tasks of 8 elems) ----
    #pragma unroll
    for (int i = 0; i < 4; ++i) {
        int idx = t + i * 256;
        int m = idx >> 4, k0 = (idx & 15) * 8;      // m 0..63
        float4 v0 = *(float4*)(stage + m * 128 + k0);
        float4 v1 = *(float4*)(stage + m * 128 + k0 + 4);
        float v[8] = { v0.x, v0.y, v0.z, v0.w, v1.x, v1.y, v1.z, v1.w };
        __nv_bfloat16 h[8], l[8];
        #pragma unroll
        for (int j = 0; j < 8; ++j) {
            h[j] = __float2bfloat16(v[j]);
            l[j] = __float2bfloat16(v[j] - __bfloat162float(h[j]));
        }
        int mblk = m >> 4, rr = m & 15, kblk = k0 >> 4, kh = (k0 >> 3) & 1;
        uint32_t off = (uint32_t)mblk * 4096u + (uint32_t)kblk * 512u
                     + (((uint32_t)rr * 32u + (uint32_t)kh * 16u) ^ ((rr & 4) ? 16u : 0u));
        *(uint4*)(sm + SM_A + off) = make_uint4(pkbf2(h[0],h[1]), pkbf2(h[2],h[3]),
                                                pkbf2(h[4],h[5]), pkbf2(h[6],h[7]));
        *(uint4*)(sm + SM_A + 16384 + off) = make_uint4(pkbf2(l[0],l[1]), pkbf2(l[2],l[3]),
                                                        pkbf2(l[4],l[5]), pkbf2(l[6],l[7]));
    }

    // ---- attention logits: 512 (r,h) tasks ----
    float dotv[2]; int rr2[2], hh2[2];
    #pragma unroll
    for (int j = 0; j < 2; ++j) {
        int idx2 = t + j * 256;
        int r = idx2 >> 3, h = idx2 & 7;
        const float* xr = stage + r * 128;
        float acc = 0.f;
        #pragma unroll 4
        for (int k = 0; k < 128; k += 4) {
            float4 xv = *(float4*)(xr + k);
            acc += xv.x * sT1[(k + 0) * 8 + h];
            acc += xv.y * sT1[(k + 1) * 8 + h];
            acc += xv.z * sT1[(k + 2) * 8 + h];
            acc += xv.w * sT1[(k + 3) * 8 + h];
        }
        dotv[j] = acc; rr2[j] = r; hh2[j] = h;
    }
    float srcv = 0.f;
    if (t < 8) {        // src term: row 0 vs T0, head = t
        const float* xr = stage;
        #pragma unroll 4
        for (int k = 0; k < 128; k += 4) {
            float4 xv = *(float4*)(xr + k);
            srcv += xv.x * sT0[(k + 0) * 8 + t];
            srcv += xv.y * sT0[(k + 1) * 8 + t];
            srcv += xv.z * sT0[(k + 2) * 8 + t];
            srcv += xv.w * sT0[(k + 3) * 8 + t];
        }
    }
    __syncthreads();    // stage fully read; A images visible
    if (t < 8) sS[t] = srcv;

    // ---- hoist A fragments (chunk-invariant): 64 regs ----
    const int mblk = w >> 1, nhalf = w & 1;
    const int ja = lane >> 3, ra = lane & 7;
    const int ml  = (ja & 1) * 8 + ra, kha = ja >> 1;
    const uint32_t arow = (((uint32_t)ml * 32u + (uint32_t)kha * 16u) ^ ((ml & 4) ? 16u : 0u));
    const uint32_t aad0 = sb + SM_A + (uint32_t)mblk * 4096u + arow;
    uint32_t a0f[8][4], a1f[8][4];
    #pragma unroll
    for (int kblk = 0; kblk < 8; ++kblk) {
        LDSM_X4(a0f[kblk], aad0 + (uint32_t)kblk * 512u);
        LDSM_X4(a1f[kblk], aad0 + 16384u + (uint32_t)kblk * 512u);
    }
    __syncthreads();    // sS visible

    // ---- logits -> attb ----
    #pragma unroll
    for (int j = 0; j < 2; ++j) {
        int n = rr2[j];
        float v = sS[hh2[j]] + dotv[j];
        v = (v >= 0.f) ? v : 0.2f * v;
        attb[hh2[j] * 64 + n] = v;
    }
    __syncthreads();

    // ---- softmax: warp w -> head w ----
    {
        int m0 = mask[b * 64 + lane];
        int m1 = mask[b * 64 + lane + 32];
        float v0 = attb[w * 64 + lane]      + (m0 == 0 ? -1e9f : 0.f);
        float v1 = attb[w * 64 + lane + 32] + (m1 == 0 ? -1e9f : 0.f);
        float mx = fmaxf(v0, v1);
        #pragma unroll
        for (int o = 16; o > 0; o >>= 1) mx = fmaxf(mx, __shfl_xor_sync(0xffffffffu, mx, o));
        float e0 = __expf(v0 - mx), e1 = __expf(v1 - mx);
        float sum = e0 + e1;
        #pragma unroll
        for (int o = 16; o > 0; o >>= 1) sum += __shfl_xor_sync(0xffffffffu, sum, o);
        float inv = 1.f / sum;
        attb[w * 64 + lane]      = e0 * inv;
        attb[w * 64 + lane + 32] = e1 * inv;
    }

    // ---- B addressing + epilogue lane mapping (permuted columns) ----
    const int nbo = (ja >> 1), khb = ja & 1;
    const uint32_t brow = (((uint32_t)ra * 32u + (uint32_t)khb * 16u) ^ ((ra & 4) ? 16u : 0u));
    const int er = lane >> 2, jj = lane & 3;
    const int ns0 = mblk * 16 + er, ns1 = ns0 + 8;   // rows 0..63
    float* ob0 = out + ((size_t)b * 64 + ns0) * 512 + nhalf * 32 + jj * 8;
    float* ob1 = out + ((size_t)b * 64 + ns1) * 512 + nhalf * 32 + jj * 8;

    // ---- mainloop: 8 N-chunks (chunk == head), double-buffered B ----
    // chunk c in buf c&1; chunk c+1 issued at top of iter c (c>=1; chunk1 below)
    __syncthreads();
    #pragma unroll
    for (int i = 0; i < 8; ++i) {                  // chunk1 -> buf1 (stage dead)
        int u = t + i * 256;
        int split = u >> 10, rem = u & 1023;
        cp_async16(sb + SM_B + 32768u + u * 16, &gWimg[split][16384 + rem * 16]);
    }
    cp_commit();

    for (int c = 0; c < 8; ++c) {
        if (c >= 1) {
            __syncthreads();                        // all warps done with chunk c-1
            if (c + 1 <= 7) {
                uint32_t dst = sb + SM_B + (uint32_t)((c + 1) & 1) * 32768u;
                #pragma unroll
                for (int i = 0; i < 8; ++i) {
                    int u = t + i * 256;
                    int split = u >> 10, rem = u & 1023;
                    cp_async16(dst + u * 16, &gWimg[split][(c + 1) * 16384 + rem * 16]);
                }
                cp_commit();
            }
        }
        if (c < 7) cp_wait<1>(); else cp_wait<0>(); // chunk c arrived
        __syncthreads();

        const uint32_t bbase = sb + SM_B + (uint32_t)(c & 1) * 32768u;
        float acc[16];
        #pragma unroll
        for (int i = 0; i < 16; ++i) acc[i] = 0.f;

        // depth-1 pipelined B stream: flat iter i = kblk*2 + ng
        uint32_t bh[2][4], bl[2][4];
        {
            uint32_t bad = bbase + (uint32_t)(nhalf * 4 + nbo) * 2048u + brow;
            LDSM_X4(bh[0], bad);
            LDSM_X4(bl[0], bad + 16384u);
        }
        #pragma unroll
        for (int i = 0; i < 16; ++i) {
            const int cur = i & 1, nxt = cur ^ 1;
            if (i < 15) {
                int kn = i + 1;
                uint32_t bad = bbase
                    + (uint32_t)(nhalf * 4 + (kn & 1) * 2 + nbo) * 2048u
                    + (uint32_t)(kn >> 1) * 256u + brow;
                LDSM_X4(bh[nxt], bad);
                LDSM_X4(bl[nxt], bad + 16384u);
            }
            const int kblk = i >> 1, go = (i & 1) * 8;
            mma16816(acc + go + 0, a0f[kblk], bh[cur][0], bh[cur][1]);  // x_hi w_hi
            mma16816(acc + go + 4, a0f[kblk], bh[cur][2], bh[cur][3]);
            mma16816(acc + go + 0, a1f[kblk], bh[cur][0], bh[cur][1]);  // x_lo w_hi
            mma16816(acc + go + 4, a1f[kblk], bh[cur][2], bh[cur][3]);
            mma16816(acc + go + 0, a0f[kblk], bl[cur][0], bl[cur][1]);  // x_hi w_lo
            mma16816(acc + go + 4, a0f[kblk], bl[cur][2], bl[cur][3]);
        }

        // ---- epilogue: permuted cols => 8 contiguous floats per thread per row ----
        float sc0 = attb[c * 64 + ns0];
        float sc1 = attb[c * 64 + ns1];
        float* o0 = ob0 + c * 64;
        float* o1 = ob1 + c * 64;
        float4 v00 = make_float4(fmaxf(acc[0]  * sc0, 0.f), fmaxf(acc[1]  * sc0, 0.f),
                                 fmaxf(acc[4]  * sc0, 0.f), fmaxf(acc[5]  * sc0, 0.f));
        float4 v01 = make_float4(fmaxf(acc[8]  * sc0, 0.f), fmaxf(acc[9]  * sc0, 0.f),
                                 fmaxf(acc[12] * sc0, 0.f), fmaxf(acc[13] * sc0, 0.f));
        float4 v10 = make_float4(fmaxf(acc[2]  * sc1, 0.f), fmaxf(acc[3]  * sc1, 0.f),
                                 fmaxf(acc[6]  * sc1, 0.f), fmaxf(acc[7]  * sc1, 0.f));
        float4 v11 = make_float4(fmaxf(acc[10] * sc1, 0.f), fmaxf(acc[11] * sc1, 0.f),
                                 fmaxf(acc[14] * sc1, 0.f), fmaxf(acc[15] * sc1, 0.f));
        *(float4*)(o0)     = v00;
        *(float4*)(o0 + 4) = v01;
        *(float4*)(o1)     = v10;
        *(float4*)(o1 + 4) = v11;
    }
}

// ---------------- launch ----------------
extern "C" void kernel_launch(void* const* d_in, const int* in_sizes, int n_in,
                              void* d_out, int out_size)
{
    const float* x    = (const float*)d_in[0];
    const float* Wlin = (const float*)d_in[1];
    const float* Watt = (const float*)d_in[2];
    const int*   mk   = (const int*)d_in[3];
    float*       out  = (float*)d_out;

    k_prep<<<96, 256>>>(Wlin, Watt);

    cudaFuncSetAttribute(agg_main, cudaFuncAttributeMaxDynamicSharedMemorySize, SMEM_BYTES);
    agg_main<<<BATCH, 256, SMEM_BYTES>>>(x, mk, out);
}